// round 13
// baseline (speedup 1.0000x reference)
#include <cuda_runtime.h>
#include <cstdint>
#include <math.h>

#define NTHREADS 1024
#define CAP      2048
#define TOPK     50
#define TOPP     0.9f
#define LOG2E    1.4426950408889634f

__device__ __forceinline__ float ex2(float x) {
    float r;
    asm("ex2.approx.f32 %0, %1;" : "=f"(r) : "f"(x));
    return r;
}

__device__ __forceinline__ uint32_t rotl_(uint32_t x, int r) { return (x << r) | (x >> (32 - r)); }

// ---------- JAX threefry2x32 (exact, 20 rounds) ----------
__device__ __forceinline__ void threefry2x32(uint32_t k0, uint32_t k1,
                                             uint32_t x0, uint32_t x1,
                                             uint32_t& o0, uint32_t& o1) {
    uint32_t k2 = k0 ^ k1 ^ 0x1BD11BDAu;
    x0 += k0; x1 += k1;
#define TFR(r) { x0 += x1; x1 = rotl_(x1, (r)); x1 ^= x0; }
    TFR(13) TFR(15) TFR(26) TFR(6)   x0 += k1; x1 += k2 + 1u;
    TFR(17) TFR(29) TFR(16) TFR(24)  x0 += k2; x1 += k0 + 2u;
    TFR(13) TFR(15) TFR(26) TFR(6)   x0 += k0; x1 += k1 + 3u;
    TFR(17) TFR(29) TFR(16) TFR(24)  x0 += k1; x1 += k2 + 4u;
    TFR(13) TFR(15) TFR(26) TFR(6)   x0 += k2; x1 += k0 + 5u;
#undef TFR
    o0 = x0; o1 = x1;
}

// noise[flat] of jax.random.exponential(fold_in(key(0),1), (B,V)) under
// jax_threefry_partitionable=True (default since JAX 0.5.0):
//   counts = iota(u64); (o0,o1) = threefry2x32(key, counts>>32, counts&0xffffffff)
//   bits32 = o0 ^ o1
//   u = bitcast(bits>>9 | 0x3f800000) - 1;  e = -log1p(-u);  clamp 1e-10
__device__ __forceinline__ float jax_exp_noise(long long flat) {
    uint32_t fk0, fk1;
    threefry2x32(0u, 0u, 0u, 1u, fk0, fk1);      // fold_in(key(0), 1) = threefry((0,0),(0,1))
    uint32_t hi = (uint32_t)((unsigned long long)flat >> 32);
    uint32_t lo = (uint32_t)flat;
    uint32_t o0, o1;
    threefry2x32(fk0, fk1, hi, lo, o0, o1);
    uint32_t bits = o0 ^ o1;                      // partitionable 32-bit fold
    float u = __uint_as_float((bits >> 9) | 0x3f800000u) - 1.0f;  // [0,1)
    return fmaxf(-log1pf(-u), 1e-10f);
}

__global__ __launch_bounds__(NTHREADS, 1)
void sampler_kernel(const float* __restrict__ logits,
                    const float* __restrict__ temps,
                    float*       __restrict__ out,   // tokens as FLOAT32 values
                    int V)
{
    const int row  = blockIdx.x;
    const int tid  = threadIdx.x;
    const int lane = tid & 31;
    const int wid  = tid >> 5;

    __shared__ float redZ[32];
    __shared__ float sZ;
    __shared__ float wtopV[64];
    __shared__ float pivotV;
    __shared__ int   nc;
    __shared__ float candVal[CAP];
    __shared__ int   candIdx[CAP];
    __shared__ float srtV[TOPK];
    __shared__ int   srtIdx[TOPK];
    __shared__ float srtP[TOPK];
    __shared__ float srtScore[TOPK];
    __shared__ int   sm_m;

    if (tid < TOPK) { srtV[tid] = -1e30f; srtIdx[tid] = 0; srtP[tid] = 0.0f; srtScore[tid] = -1.0f; }
    if (tid == 0) nc = 0;

    const float NEG = __int_as_float(0xff800000);       // -inf
    const float C   = (1.0f / temps[row]) * LOG2E;      // temperature folded with log2(e)
    const float* x  = logits + (long long)row * V;

    // ---------- Phase A: one pass: Z = sum(exp2(x*C)); per-thread top-8 raw logits ----------
    float zsum = 0.0f;
    float thr[8]; int ti[8];
#pragma unroll
    for (int j = 0; j < 8; j++) { thr[j] = NEG; ti[j] = -1; }

    const int V4 = V >> 2;
    const float4* x4 = (const float4*)x;
#pragma unroll 2
    for (int i = tid; i < V4; i += NTHREADS) {
        float4 v = x4[i];
#pragma unroll
        for (int c = 0; c < 4; c++) {
            float xv = (c == 0) ? v.x : (c == 1) ? v.y : (c == 2) ? v.z : v.w;
            zsum += ex2(xv * C);
            if (xv > thr[7]) {
                thr[7] = xv; ti[7] = i * 4 + c;
#pragma unroll
                for (int j = 7; j > 0; --j)
                    if (thr[j] > thr[j - 1]) {
                        float tv = thr[j]; thr[j] = thr[j - 1]; thr[j - 1] = tv;
                        int   qq = ti[j];  ti[j]  = ti[j - 1];  ti[j - 1]  = qq;
                    }
            }
        }
    }
    for (int i = V4 * 4 + tid; i < V; i += NTHREADS) {
        float xv = x[i];
        zsum += ex2(xv * C);
        if (xv > thr[7]) {
            thr[7] = xv; ti[7] = i;
#pragma unroll
            for (int j = 7; j > 0; --j)
                if (thr[j] > thr[j - 1]) {
                    float tv = thr[j]; thr[j] = thr[j - 1]; thr[j - 1] = tv;
                    int   qq = ti[j];  ti[j]  = ti[j - 1];  ti[j - 1]  = qq;
                }
        }
    }

    // ---------- Phase B: warp-reduce Z; per-warp top-2 ----------
#pragma unroll
    for (int off = 16; off; off >>= 1) zsum += __shfl_xor_sync(0xffffffffu, zsum, off);
    if (lane == 0) redZ[wid] = zsum;

    float w1 = thr[0];
#pragma unroll
    for (int off = 16; off; off >>= 1) w1 = fmaxf(w1, __shfl_xor_sync(0xffffffffu, w1, off));
    unsigned mm = __ballot_sync(0xffffffffu, thr[0] == w1);
    int leader  = __ffs(mm) - 1;
    float c2 = (lane == leader) ? thr[1] : thr[0];
    float w2 = c2;
#pragma unroll
    for (int off = 16; off; off >>= 1) w2 = fmaxf(w2, __shfl_xor_sync(0xffffffffu, w2, off));
    if (lane == 0) { wtopV[2 * wid] = w1; wtopV[2 * wid + 1] = w2; }
    __syncthreads();

    // ---------- Phase C: block Z; pivot = rank-49 among 64 warp-top-2 values ----------
    if (wid == 0) {
        float z2 = redZ[lane];
#pragma unroll
        for (int off = 16; off; off >>= 1) z2 += __shfl_xor_sync(0xffffffffu, z2, off);
        if (lane == 0) sZ = z2;

        for (int e = lane; e < 64; e += 32) {
            float kv = wtopV[e];
            int r = 0;
            for (int t = 0; t < 64; t++) {
                float kt = wtopV[t];
                r += (kt > kv) || (kt == kv && t < e);
            }
            if (r == (TOPK - 1)) pivotV = kv;   // pivot <= true 50th-largest
        }
    }
    __syncthreads();

    // ---------- Phase D: compact entries >= pivot ----------
    float pv = pivotV;
    int cnt = 0;
#pragma unroll
    for (int j = 0; j < 8; j++) cnt += (thr[j] >= pv && ti[j] >= 0) ? 1 : 0;
    int base = 0;
    if (cnt) base = atomicAdd(&nc, cnt);
#pragma unroll
    for (int j = 0; j < 8; j++) {
        if (j < cnt) {
            int p = base + j;
            if (p < CAP) { candVal[p] = thr[j]; candIdx[p] = ti[j]; }
        }
    }
    __syncthreads();
    int n2 = nc < CAP ? nc : CAP;

    // ---------- Phase E: exact ranking (value desc, index asc) -> sorted top-50 ----------
    for (int j = tid; j < n2; j += NTHREADS) {
        float vj = candVal[j]; int ij = candIdx[j];
        int r = 0;
        for (int t = 0; t < n2; t++) {
            float vt = candVal[t]; int it = candIdx[t];
            r += (vt > vj) || (vt == vj && it < ij);
        }
        if (r < TOPK) { srtV[r] = vj; srtIdx[r] = ij; }
    }
    __syncthreads();

    // ---------- Phase F: top-p cumsum -> kept count m ----------
    if (tid == 0) {
        float Z = sZ;
        int Keff = (TOPK < n2) ? TOPK : n2;
        if (Keff < 1) Keff = 1;
        float cum = 0.0f;
        int m = 1;
        for (int r = 0; r < Keff; r++) {
            float p = exp2f(srtV[r] * C) / Z;
            srtP[r] = p;
            cum += p;
            if (r == 0)           m = 1;
            else if (cum <= TOPP) m = r + 1;
            else break;
        }
        sm_m = m;
    }
    __syncthreads();

    // ---------- Phase G: argmax(p / exp_noise) over kept set ----------
    int m = sm_m;
    if (tid < m) {
        long long flat = (long long)row * V + (long long)srtIdx[tid];
        srtScore[tid] = srtP[tid] / jax_exp_noise(flat);
    }
    __syncthreads();
    if (tid == 0) {
        float best   = srtScore[0];
        int bestIdx  = srtIdx[0];
        for (int r = 1; r < m; r++) {
            float sc = srtScore[r]; int iv = srtIdx[r];
            if (sc > best || (sc == best && iv < bestIdx)) { best = sc; bestIdx = iv; }
        }
        out[row] = (float)bestIdx;         // token as float32 VALUE (not bit pattern)
    }
}

extern "C" void kernel_launch(void* const* d_in, const int* in_sizes, int n_in,
                              void* d_out, int out_size) {
    // logits = largest input; temps = the largest of the remaining inputs
    // (temps has B elements; top_k, if materialized, has 1). d_in[2] never read.
    int li = 0;
    for (int i = 1; i < n_in; i++) if (in_sizes[i] > in_sizes[li]) li = i;
    int te = -1;
    for (int i = 0; i < n_in; i++) {
        if (i == li) continue;
        if (te < 0 || in_sizes[i] > in_sizes[te]) te = i;
    }
    if (te < 0) te = (li == 0) ? 1 : 0;

    const float* logits = (const float*)d_in[li];
    const float* temps  = (const float*)d_in[te];
    float*       out    = (float*)d_out;

    int B = in_sizes[te];
    int V = in_sizes[li] / B;

    sampler_kernel<<<B, NTHREADS>>>(logits, temps, out, V);
}

// round 14
// speedup vs baseline: 2.1019x; 2.1019x over previous
#include <cuda_runtime.h>
#include <cstdint>
#include <math.h>

#define NTHREADS 1024
#define CAP      2048
#define TOPK     50
#define TOPP     0.9f
#define LOG2E    1.4426950408889634f

__device__ __forceinline__ float ex2(float x) {
    float r;
    asm("ex2.approx.f32 %0, %1;" : "=f"(r) : "f"(x));
    return r;
}

__device__ __forceinline__ uint32_t rotl_(uint32_t x, int r) { return (x << r) | (x >> (32 - r)); }

// ---------- JAX threefry2x32 (exact, 20 rounds) ----------
__device__ __forceinline__ void threefry2x32(uint32_t k0, uint32_t k1,
                                             uint32_t x0, uint32_t x1,
                                             uint32_t& o0, uint32_t& o1) {
    uint32_t k2 = k0 ^ k1 ^ 0x1BD11BDAu;
    x0 += k0; x1 += k1;
#define TFR(r) { x0 += x1; x1 = rotl_(x1, (r)); x1 ^= x0; }
    TFR(13) TFR(15) TFR(26) TFR(6)   x0 += k1; x1 += k2 + 1u;
    TFR(17) TFR(29) TFR(16) TFR(24)  x0 += k2; x1 += k0 + 2u;
    TFR(13) TFR(15) TFR(26) TFR(6)   x0 += k0; x1 += k1 + 3u;
    TFR(17) TFR(29) TFR(16) TFR(24)  x0 += k1; x1 += k2 + 4u;
    TFR(13) TFR(15) TFR(26) TFR(6)   x0 += k2; x1 += k0 + 5u;
#undef TFR
    o0 = x0; o1 = x1;
}

// noise[flat] of jax.random.exponential(fold_in(key(0),1), (B,V)),
// jax_threefry_partitionable path: bits = o0 ^ o1 of threefry(key, flat>>32, flat&mask)
__device__ __forceinline__ float jax_exp_noise(long long flat) {
    uint32_t fk0, fk1;
    threefry2x32(0u, 0u, 0u, 1u, fk0, fk1);      // fold_in(key(0), 1)
    uint32_t hi = (uint32_t)((unsigned long long)flat >> 32);
    uint32_t lo = (uint32_t)flat;
    uint32_t o0, o1;
    threefry2x32(fk0, fk1, hi, lo, o0, o1);
    uint32_t bits = o0 ^ o1;
    float u = __uint_as_float((bits >> 9) | 0x3f800000u) - 1.0f;  // [0,1)
    return fmaxf(-log1pf(-u), 1e-10f);
}

__global__ __launch_bounds__(NTHREADS, 1)
void sampler_kernel(const float* __restrict__ logits,
                    const float* __restrict__ temps,
                    float*       __restrict__ out,   // tokens as float32 values
                    int V)
{
    const int row  = blockIdx.x;
    const int tid  = threadIdx.x;
    const int lane = tid & 31;
    const int wid  = tid >> 5;

    __shared__ float redZ[32];
    __shared__ float sZ;
    __shared__ float wtopV[64];
    __shared__ float pivotV;
    __shared__ int   nc;
    __shared__ float candVal[CAP];
    __shared__ int   candIdx[CAP];
    __shared__ float srtV[TOPK];
    __shared__ int   srtIdx[TOPK];
    __shared__ float srtP[TOPK];
    __shared__ float srtScore[TOPK];
    __shared__ int   sm_m;

    if (tid < TOPK) { srtV[tid] = -1e30f; srtIdx[tid] = 0; srtP[tid] = 0.0f; srtScore[tid] = -1.0f; }
    if (tid == 0) nc = 0;

    const float NEG = -1e30f;
    const float C   = (1.0f / temps[row]) * LOG2E;      // temperature folded with log2(e)
    const float* x  = logits + (long long)row * V;
    const int V4    = V >> 2;
    const float4* x4 = (const float4*)x;

    // ---------- Pass 1 (DRAM): Z = sum(exp2(x*C)); branch-free per-thread top-2 ----------
    float z0 = 0.0f, z1 = 0.0f, z2 = 0.0f, z3 = 0.0f;
    float mx1 = NEG, mx2 = NEG;          // top-2 values (no indices needed)

#pragma unroll 2
    for (int i = tid; i < V4; i += NTHREADS) {
        float4 v = x4[i];
        z0 += ex2(v.x * C);
        z1 += ex2(v.y * C);
        z2 += ex2(v.z * C);
        z3 += ex2(v.w * C);
        // branch-free top-2: mx2 = max(mx2, min(mx1, v)); mx1 = max(mx1, v)
        mx2 = fmaxf(mx2, fminf(mx1, v.x)); mx1 = fmaxf(mx1, v.x);
        mx2 = fmaxf(mx2, fminf(mx1, v.y)); mx1 = fmaxf(mx1, v.y);
        mx2 = fmaxf(mx2, fminf(mx1, v.z)); mx1 = fmaxf(mx1, v.z);
        mx2 = fmaxf(mx2, fminf(mx1, v.w)); mx1 = fmaxf(mx1, v.w);
    }
    for (int i = V4 * 4 + tid; i < V; i += NTHREADS) {
        float xv = x[i];
        z0 += ex2(xv * C);
        mx2 = fmaxf(mx2, fminf(mx1, xv)); mx1 = fmaxf(mx1, xv);
    }
    float zsum = (z0 + z1) + (z2 + z3);

    // ---------- warp-reduce Z; per-warp top-2 ----------
#pragma unroll
    for (int off = 16; off; off >>= 1) zsum += __shfl_xor_sync(0xffffffffu, zsum, off);
    if (lane == 0) redZ[wid] = zsum;

    float w1 = mx1;
#pragma unroll
    for (int off = 16; off; off >>= 1) w1 = fmaxf(w1, __shfl_xor_sync(0xffffffffu, w1, off));
    unsigned mm = __ballot_sync(0xffffffffu, mx1 == w1);
    int leader  = __ffs(mm) - 1;
    float c2 = (lane == leader) ? mx2 : mx1;
    float w2 = c2;
#pragma unroll
    for (int off = 16; off; off >>= 1) w2 = fmaxf(w2, __shfl_xor_sync(0xffffffffu, w2, off));
    if (lane == 0) { wtopV[2 * wid] = w1; wtopV[2 * wid + 1] = w2; }
    __syncthreads();

    // ---------- block Z; pivot = rank-49 among 64 per-warp top-2 values ----------
    if (wid == 0) {
        float zz = redZ[lane];
#pragma unroll
        for (int off = 16; off; off >>= 1) zz += __shfl_xor_sync(0xffffffffu, zz, off);
        if (lane == 0) sZ = zz;

        for (int e = lane; e < 64; e += 32) {
            float kv = wtopV[e];
            int r = 0;
            for (int t = 0; t < 64; t++) {
                float kt = wtopV[t];
                r += (kt > kv) || (kt == kv && t < e);
            }
            if (r == (TOPK - 1)) pivotV = kv;   // pivot <= true 50th-largest
        }
    }
    __syncthreads();

    // ---------- Pass 2 (L2-resident): gather all elements >= pivot ----------
    const float pv = pivotV;
#pragma unroll 2
    for (int i = tid; i < V4; i += NTHREADS) {
        float4 v = x4[i];
        float vm = fmaxf(fmaxf(v.x, v.y), fmaxf(v.z, v.w));
        if (vm >= pv) {                                   // rare (~100 hits per row)
            if (v.x >= pv) { int p = atomicAdd(&nc, 1); if (p < CAP) { candVal[p] = v.x; candIdx[p] = 4 * i;     } }
            if (v.y >= pv) { int p = atomicAdd(&nc, 1); if (p < CAP) { candVal[p] = v.y; candIdx[p] = 4 * i + 1; } }
            if (v.z >= pv) { int p = atomicAdd(&nc, 1); if (p < CAP) { candVal[p] = v.z; candIdx[p] = 4 * i + 2; } }
            if (v.w >= pv) { int p = atomicAdd(&nc, 1); if (p < CAP) { candVal[p] = v.w; candIdx[p] = 4 * i + 3; } }
        }
    }
    for (int i = V4 * 4 + tid; i < V; i += NTHREADS) {
        float xv = x[i];
        if (xv >= pv) { int p = atomicAdd(&nc, 1); if (p < CAP) { candVal[p] = xv; candIdx[p] = i; } }
    }
    __syncthreads();
    int n2 = nc < CAP ? nc : CAP;

    // ---------- exact ranking (value desc, index asc) -> sorted top-50 ----------
    for (int j = tid; j < n2; j += NTHREADS) {
        float vj = candVal[j]; int ij = candIdx[j];
        int r = 0;
        for (int t = 0; t < n2; t++) {
            float vt = candVal[t]; int it = candIdx[t];
            r += (vt > vj) || (vt == vj && it < ij);
        }
        if (r < TOPK) { srtV[r] = vj; srtIdx[r] = ij; }
    }
    __syncthreads();

    // ---------- top-p cumsum -> kept count m ----------
    if (tid == 0) {
        float Z = sZ;
        int Keff = (TOPK < n2) ? TOPK : n2;
        if (Keff < 1) Keff = 1;
        float cum = 0.0f;
        int m = 1;
        for (int r = 0; r < Keff; r++) {
            float p = exp2f(srtV[r] * C) / Z;
            srtP[r] = p;
            cum += p;
            if (r == 0)           m = 1;
            else if (cum <= TOPP) m = r + 1;
            else break;
        }
        sm_m = m;
    }
    __syncthreads();

    // ---------- argmax(p / exp_noise) over kept set ----------
    int m = sm_m;
    if (tid < m) {
        long long flat = (long long)row * V + (long long)srtIdx[tid];
        srtScore[tid] = srtP[tid] / jax_exp_noise(flat);
    }
    __syncthreads();
    if (tid == 0) {
        float best   = srtScore[0];
        int bestIdx  = srtIdx[0];
        for (int r = 1; r < m; r++) {
            float sc = srtScore[r]; int iv = srtIdx[r];
            if (sc > best || (sc == best && iv < bestIdx)) { best = sc; bestIdx = iv; }
        }
        out[row] = (float)bestIdx;         // token as float32 value
    }
}

extern "C" void kernel_launch(void* const* d_in, const int* in_sizes, int n_in,
                              void* d_out, int out_size) {
    // logits = largest input; temps = largest remaining input. d_in[2] never read.
    int li = 0;
    for (int i = 1; i < n_in; i++) if (in_sizes[i] > in_sizes[li]) li = i;
    int te = -1;
    for (int i = 0; i < n_in; i++) {
        if (i == li) continue;
        if (te < 0 || in_sizes[i] > in_sizes[te]) te = i;
    }
    if (te < 0) te = (li == 0) ? 1 : 0;

    const float* logits = (const float*)d_in[li];
    const float* temps  = (const float*)d_in[te];
    float*       out    = (float*)d_out;

    int B = in_sizes[te];
    int V = in_sizes[li] / B;

    sampler_kernel<<<B, NTHREADS>>>(logits, temps, out, V);
}

// round 15
// speedup vs baseline: 2.3312x; 1.1091x over previous
#include <cuda_runtime.h>
#include <cstdint>
#include <math.h>

#define NTHREADS 1024
#define CAP      2048
#define TOPK     50
#define TOPP     0.9f
#define LOG2E    1.4426950408889634f

__device__ __forceinline__ float ex2(float x) {
    float r;
    asm("ex2.approx.f32 %0, %1;" : "=f"(r) : "f"(x));
    return r;
}

__device__ __forceinline__ uint32_t rotl_(uint32_t x, int r) { return (x << r) | (x >> (32 - r)); }

// ---------- JAX threefry2x32 (exact, 20 rounds) ----------
__device__ __forceinline__ void threefry2x32(uint32_t k0, uint32_t k1,
                                             uint32_t x0, uint32_t x1,
                                             uint32_t& o0, uint32_t& o1) {
    uint32_t k2 = k0 ^ k1 ^ 0x1BD11BDAu;
    x0 += k0; x1 += k1;
#define TFR(r) { x0 += x1; x1 = rotl_(x1, (r)); x1 ^= x0; }
    TFR(13) TFR(15) TFR(26) TFR(6)   x0 += k1; x1 += k2 + 1u;
    TFR(17) TFR(29) TFR(16) TFR(24)  x0 += k2; x1 += k0 + 2u;
    TFR(13) TFR(15) TFR(26) TFR(6)   x0 += k0; x1 += k1 + 3u;
    TFR(17) TFR(29) TFR(16) TFR(24)  x0 += k1; x1 += k2 + 4u;
    TFR(13) TFR(15) TFR(26) TFR(6)   x0 += k2; x1 += k0 + 5u;
#undef TFR
    o0 = x0; o1 = x1;
}

// noise[flat] of jax.random.exponential(fold_in(key(0),1), (B,V)),
// jax_threefry_partitionable path: bits = o0 ^ o1 of threefry(key, flat>>32, flat&mask)
__device__ __forceinline__ float jax_exp_noise(long long flat) {
    uint32_t fk0, fk1;
    threefry2x32(0u, 0u, 0u, 1u, fk0, fk1);      // fold_in(key(0), 1)
    uint32_t hi = (uint32_t)((unsigned long long)flat >> 32);
    uint32_t lo = (uint32_t)flat;
    uint32_t o0, o1;
    threefry2x32(fk0, fk1, hi, lo, o0, o1);
    uint32_t bits = o0 ^ o1;
    float u = __uint_as_float((bits >> 9) | 0x3f800000u) - 1.0f;  // [0,1)
    return fmaxf(-log1pf(-u), 1e-10f);
}

__global__ __launch_bounds__(NTHREADS, 1)
void sampler_kernel(const float* __restrict__ logits,
                    const float* __restrict__ temps,
                    float*       __restrict__ out,   // tokens as float32 values
                    int V)
{
    const int row  = blockIdx.x;
    const int tid  = threadIdx.x;
    const int lane = tid & 31;
    const int wid  = tid >> 5;

    __shared__ float redZ[32];
    __shared__ float sZ;
    __shared__ float wtopV[64];
    __shared__ float pivotV;
    __shared__ int   nc;
    __shared__ float candVal[CAP];
    __shared__ int   candIdx[CAP];
    __shared__ float srtV[TOPK];
    __shared__ int   srtIdx[TOPK];
    __shared__ float srtP[TOPK];
    __shared__ float srtScore[TOPK];
    __shared__ int   sm_m;

    if (tid < TOPK) { srtV[tid] = -1e30f; srtIdx[tid] = 0; srtP[tid] = 0.0f; srtScore[tid] = -1.0f; }
    if (tid == 0) nc = 0;

    const float NEG = -1e30f;
    const float C   = (1.0f / temps[row]) * LOG2E;      // temperature folded with log2(e)
    const float* x  = logits + (long long)row * V;
    const int V4    = V >> 2;
    const float4* x4 = (const float4*)x;

    // ---------- Pass 1 (DRAM): Z = sum(exp2(x*C)); branch-free per-thread top-2 ----------
    // Software-pipelined: 4 independent LDG.128 in flight per warp (16 KB/SM MLP).
    float z0 = 0.0f, z1 = 0.0f, z2 = 0.0f, z3 = 0.0f;
    float mx1 = NEG, mx2 = NEG;

#define P1_BODY(v)                                                         \
    {                                                                      \
        z0 += ex2((v).x * C); z1 += ex2((v).y * C);                        \
        z2 += ex2((v).z * C); z3 += ex2((v).w * C);                        \
        mx2 = fmaxf(mx2, fminf(mx1, (v).x)); mx1 = fmaxf(mx1, (v).x);      \
        mx2 = fmaxf(mx2, fminf(mx1, (v).y)); mx1 = fmaxf(mx1, (v).y);      \
        mx2 = fmaxf(mx2, fminf(mx1, (v).z)); mx1 = fmaxf(mx1, (v).z);      \
        mx2 = fmaxf(mx2, fminf(mx1, (v).w)); mx1 = fmaxf(mx1, (v).w);      \
    }

    int i = tid;
    for (; i + 3 * NTHREADS < V4; i += 4 * NTHREADS) {
        float4 a = x4[i];
        float4 b = x4[i +     NTHREADS];
        float4 c = x4[i + 2 * NTHREADS];
        float4 d = x4[i + 3 * NTHREADS];
        P1_BODY(a) P1_BODY(b) P1_BODY(c) P1_BODY(d)
    }
    for (; i < V4; i += NTHREADS) {
        float4 a = x4[i];
        P1_BODY(a)
    }
    for (int t = V4 * 4 + tid; t < V; t += NTHREADS) {
        float xv = x[t];
        z0 += ex2(xv * C);
        mx2 = fmaxf(mx2, fminf(mx1, xv)); mx1 = fmaxf(mx1, xv);
    }
#undef P1_BODY
    float zsum = (z0 + z1) + (z2 + z3);

    // ---------- warp-reduce Z; per-warp top-2 ----------
#pragma unroll
    for (int off = 16; off; off >>= 1) zsum += __shfl_xor_sync(0xffffffffu, zsum, off);
    if (lane == 0) redZ[wid] = zsum;

    float w1 = mx1;
#pragma unroll
    for (int off = 16; off; off >>= 1) w1 = fmaxf(w1, __shfl_xor_sync(0xffffffffu, w1, off));
    unsigned mm = __ballot_sync(0xffffffffu, mx1 == w1);
    int leader  = __ffs(mm) - 1;
    float c2 = (lane == leader) ? mx2 : mx1;
    float w2 = c2;
#pragma unroll
    for (int off = 16; off; off >>= 1) w2 = fmaxf(w2, __shfl_xor_sync(0xffffffffu, w2, off));
    if (lane == 0) { wtopV[2 * wid] = w1; wtopV[2 * wid + 1] = w2; }
    __syncthreads();

    // ---------- block Z; pivot = rank-49 among 64 per-warp top-2 values ----------
    if (wid == 0) {
        float zz = redZ[lane];
#pragma unroll
        for (int off = 16; off; off >>= 1) zz += __shfl_xor_sync(0xffffffffu, zz, off);
        if (lane == 0) sZ = zz;

        for (int e = lane; e < 64; e += 32) {
            float kv = wtopV[e];
            int r = 0;
            for (int t = 0; t < 64; t++) {
                float kt = wtopV[t];
                r += (kt > kv) || (kt == kv && t < e);
            }
            if (r == (TOPK - 1)) pivotV = kv;   // 50th-largest of 64 distinct-pos values <= s50
        }
    }
    __syncthreads();

    // ---------- Pass 2 (L2-resident): gather all elements >= pivot, batch-4 loads ----------
    const float pv = pivotV;

#define P2_BODY(v, base)                                                                            \
    {                                                                                               \
        float vm = fmaxf(fmaxf((v).x, (v).y), fmaxf((v).z, (v).w));                                 \
        if (vm >= pv) {                                                                             \
            if ((v).x >= pv) { int p = atomicAdd(&nc, 1); if (p < CAP) { candVal[p] = (v).x; candIdx[p] = (base);     } } \
            if ((v).y >= pv) { int p = atomicAdd(&nc, 1); if (p < CAP) { candVal[p] = (v).y; candIdx[p] = (base) + 1; } } \
            if ((v).z >= pv) { int p = atomicAdd(&nc, 1); if (p < CAP) { candVal[p] = (v).z; candIdx[p] = (base) + 2; } } \
            if ((v).w >= pv) { int p = atomicAdd(&nc, 1); if (p < CAP) { candVal[p] = (v).w; candIdx[p] = (base) + 3; } } \
        }                                                                                           \
    }

    i = tid;
    for (; i + 3 * NTHREADS < V4; i += 4 * NTHREADS) {
        float4 a = x4[i];
        float4 b = x4[i +     NTHREADS];
        float4 c = x4[i + 2 * NTHREADS];
        float4 d = x4[i + 3 * NTHREADS];
        P2_BODY(a, 4 * i)
        P2_BODY(b, 4 * (i + NTHREADS))
        P2_BODY(c, 4 * (i + 2 * NTHREADS))
        P2_BODY(d, 4 * (i + 3 * NTHREADS))
    }
    for (; i < V4; i += NTHREADS) {
        float4 a = x4[i];
        P2_BODY(a, 4 * i)
    }
    for (int t = V4 * 4 + tid; t < V; t += NTHREADS) {
        float xv = x[t];
        if (xv >= pv) { int p = atomicAdd(&nc, 1); if (p < CAP) { candVal[p] = xv; candIdx[p] = t; } }
    }
#undef P2_BODY
    __syncthreads();
    int n2 = nc < CAP ? nc : CAP;

    // ---------- exact ranking (value desc, index asc) -> sorted top-50 ----------
    for (int j = tid; j < n2; j += NTHREADS) {
        float vj = candVal[j]; int ij = candIdx[j];
        int r = 0;
        for (int t = 0; t < n2; t++) {
            float vt = candVal[t]; int it = candIdx[t];
            r += (vt > vj) || (vt == vj && it < ij);
        }
        if (r < TOPK) { srtV[r] = vj; srtIdx[r] = ij; }
    }
    __syncthreads();

    // ---------- top-p cumsum -> kept count m ----------
    if (tid == 0) {
        float Z = sZ;
        int Keff = (TOPK < n2) ? TOPK : n2;
        if (Keff < 1) Keff = 1;
        float cum = 0.0f;
        int m = 1;
        for (int r = 0; r < Keff; r++) {
            float p = exp2f(srtV[r] * C) / Z;
            srtP[r] = p;
            cum += p;
            if (r == 0)           m = 1;
            else if (cum <= TOPP) m = r + 1;
            else break;
        }
        sm_m = m;
    }
    __syncthreads();

    // ---------- argmax(p / exp_noise) over kept set ----------
    int m = sm_m;
    if (tid < m) {
        long long flat = (long long)row * V + (long long)srtIdx[tid];
        srtScore[tid] = srtP[tid] / jax_exp_noise(flat);
    }
    __syncthreads();
    if (tid == 0) {
        float best   = srtScore[0];
        int bestIdx  = srtIdx[0];
        for (int r = 1; r < m; r++) {
            float sc = srtScore[r]; int iv = srtIdx[r];
            if (sc > best || (sc == best && iv < bestIdx)) { best = sc; bestIdx = iv; }
        }
        out[row] = (float)bestIdx;         // token as float32 value
    }
}

extern "C" void kernel_launch(void* const* d_in, const int* in_sizes, int n_in,
                              void* d_out, int out_size) {
    // logits = largest input; temps = largest remaining input. d_in[2] never read.
    int li = 0;
    for (int i = 1; i < n_in; i++) if (in_sizes[i] > in_sizes[li]) li = i;
    int te = -1;
    for (int i = 0; i < n_in; i++) {
        if (i == li) continue;
        if (te < 0 || in_sizes[i] > in_sizes[te]) te = i;
    }
    if (te < 0) te = (li == 0) ? 1 : 0;

    const float* logits = (const float*)d_in[li];
    const float* temps  = (const float*)d_in[te];
    float*       out    = (float*)d_out;

    int B = in_sizes[te];
    int V = in_sizes[li] / B;

    sampler_kernel<<<B, NTHREADS>>>(logits, temps, out, V);
}